// round 3
// baseline (speedup 1.0000x reference)
#include <cuda_runtime.h>

// Problem constants
#define Bp   8
#define Np   1024
#define Dp   512
#define Hp   8
#define DHp  64
#define Mp   (Bp * Np)          // 8192 rows

// Scratch: Q/K/V in [B, H, N, DH] layout (16 MB each, static device globals — no allocs)
__device__ float g_q[Bp * Hp * Np * DHp];
__device__ float g_k[Bp * Hp * Np * DHp];
__device__ float g_v[Bp * Hp * Np * DHp];

// ---------------------------------------------------------------------------
// Kernel 1: fused QKV projection GEMM.
//   C[m, c] = sum_k x[m,k] * W[k,c] + bias[c], written into [B,H,N,DH] scratch.
// Tiling: BM=64, BN=64, BK=16, 256 threads, 4x4 micro-tile per thread.
// blockIdx.z selects which of {Q,K,V}.
// ---------------------------------------------------------------------------
__global__ __launch_bounds__(256) void qkv_kernel(
    const float* __restrict__ x,
    const float* __restrict__ Wq, const float* __restrict__ bq,
    const float* __restrict__ Wk, const float* __restrict__ bk,
    const float* __restrict__ Wv, const float* __restrict__ bv)
{
    __shared__ float Xs[16][68];   // [k][m], padded stride 68
    __shared__ float Ws[16][64];   // [k][n]

    const int which = blockIdx.z;
    const float* W    = (which == 0) ? Wq : (which == 1) ? Wk : Wv;
    const float* bias = (which == 0) ? bq : (which == 1) ? bk : bv;
    float* outp       = (which == 0) ? g_q : (which == 1) ? g_k : g_v;

    const int m0 = blockIdx.y * 64;
    const int nb = blockIdx.x * 64;
    const int tid = threadIdx.x;
    const int tx = tid & 15;       // n-fragment selector
    const int ty = tid >> 4;       // m-fragment selector

    float acc[4][4];
    #pragma unroll
    for (int i = 0; i < 4; i++)
        #pragma unroll
        for (int j = 0; j < 4; j++) acc[i][j] = 0.0f;

    const int xcol = tid & 15, xrow0 = tid >> 4;   // X tile loader mapping
    const int wcol = tid & 63, wrow0 = tid >> 6;   // W tile loader mapping

    for (int kt = 0; kt < Dp; kt += 16) {
        // Load X tile [64 m][16 k] transposed into Xs[k][m]
        #pragma unroll
        for (int p = 0; p < 4; p++) {
            int row = xrow0 + p * 16;
            Xs[xcol][row] = x[(size_t)(m0 + row) * Dp + kt + xcol];
        }
        // Load W tile [16 k][64 n]
        #pragma unroll
        for (int p = 0; p < 4; p++) {
            int r = wrow0 + p * 4;
            Ws[r][wcol] = W[(size_t)(kt + r) * Dp + nb + wcol];
        }
        __syncthreads();

        #pragma unroll
        for (int k = 0; k < 16; k++) {
            float a[4], w[4];
            *(float4*)a = *(const float4*)&Xs[k][ty * 4];
            *(float4*)w = *(const float4*)&Ws[k][tx * 4];
            #pragma unroll
            for (int i = 0; i < 4; i++)
                #pragma unroll
                for (int j = 0; j < 4; j++)
                    acc[i][j] = fmaf(a[i], w[j], acc[i][j]);
        }
        __syncthreads();
    }

    // Epilogue: add bias, write to [B,H,N,DH] scratch.
    // nb is 64-aligned so each n-tile is exactly one head: h = nb/64, d = tx*4+j.
    float b4[4];
    #pragma unroll
    for (int j = 0; j < 4; j++) b4[j] = bias[nb + tx * 4 + j];
    const int h = nb >> 6;

    #pragma unroll
    for (int i = 0; i < 4; i++) {
        int gm = m0 + ty * 4 + i;
        int bb = gm >> 10;          // batch
        int nn = gm & 1023;         // seq pos
        float4 o;
        o.x = acc[i][0] + b4[0];
        o.y = acc[i][1] + b4[1];
        o.z = acc[i][2] + b4[2];
        o.w = acc[i][3] + b4[3];
        size_t addr = (((size_t)(bb * Hp + h)) * Np + nn) * DHp + tx * 4;
        *(float4*)&outp[addr] = o;
    }
}

// ---------------------------------------------------------------------------
// Kernel 2: flash attention per (b,h), 64 Q rows per CTA, 64-key tiles.
//   scores = Q K^T (NO 1/sqrt(dh) scaling per reference), online softmax, O = P V.
// smem (dynamic, 68,864 B): Qt[d][q], Kt[d][k], Vs[k][d], Ps[q][k]
// Thread map: tx = tid&15 -> 4 k-cols (S) / 4 d-cols (O); ty = tid>>4 -> 4 q-rows.
// Row-group of 16 tx-threads lives in one aligned 16-lane warp half -> shfl_xor ok.
// ---------------------------------------------------------------------------
#define QS 68
#define KS 68
#define VS 68
#define PS 65
#define ATTN_SMEM ((3 * 64 * 68 + 64 * 65) * 4)   // 68,864 bytes

__global__ __launch_bounds__(256) void attn_kernel(float* __restrict__ out)
{
    extern __shared__ float sm[];
    float* Qt = sm;                 // [64 d][QS]
    float* Kt = Qt + 64 * QS;       // [64 d][KS]
    float* Vs = Kt + 64 * KS;       // [64 k][VS]
    float* Ps = Vs + 64 * VS;       // [64 q][PS]

    const int q0 = blockIdx.x * 64;
    const int bh = blockIdx.y;                 // b*H + h
    const int b  = bh >> 3, h = bh & 7;
    const int tid = threadIdx.x;
    const int tx = tid & 15, ty = tid >> 4;

    const float* gq = g_q + ((size_t)bh * Np + q0) * DHp;
    const float* gk = g_k + (size_t)bh * Np * DHp;
    const float* gv = g_v + (size_t)bh * Np * DHp;

    // Load Q tile [64 q][64 d] transposed into Qt[d][q]
    for (int idx = tid; idx < 64 * 64; idx += 256) {
        int q = idx >> 6, d = idx & 63;
        Qt[d * QS + q] = gq[idx];
    }

    float m_i[4], l_i[4], acc[4][4];
    #pragma unroll
    for (int i = 0; i < 4; i++) {
        m_i[i] = -1e30f; l_i[i] = 0.0f;
        #pragma unroll
        for (int j = 0; j < 4; j++) acc[i][j] = 0.0f;
    }

    const float LOG2E = 1.44269504088896340736f;

    for (int kt = 0; kt < Np; kt += 64) {
        __syncthreads();   // previous iter's Kt/Vs/Ps reads done (also orders Q store 1st iter)

        // Load K tile transposed Kt[d][k], V tile row-major Vs[k][d]
        for (int idx = tid; idx < 64 * 64; idx += 256) {
            int k = idx >> 6, d = idx & 63;
            Kt[d * KS + k] = gk[kt * DHp + idx];
            Vs[k * VS + d] = gv[kt * DHp + idx];
        }
        __syncthreads();

        // S = Q K^T  (4x4 per thread, k-inner over d)
        float s[4][4];
        #pragma unroll
        for (int i = 0; i < 4; i++)
            #pragma unroll
            for (int j = 0; j < 4; j++) s[i][j] = 0.0f;

        #pragma unroll 8
        for (int d = 0; d < 64; d++) {
            float a[4], kf[4];
            *(float4*)a  = *(const float4*)&Qt[d * QS + ty * 4];
            *(float4*)kf = *(const float4*)&Kt[d * KS + tx * 4];
            #pragma unroll
            for (int i = 0; i < 4; i++)
                #pragma unroll
                for (int j = 0; j < 4; j++)
                    s[i][j] = fmaf(a[i], kf[j], s[i][j]);
        }

        // Online softmax per q-row (reduce across 16 tx lanes of warp half)
        #pragma unroll
        for (int i = 0; i < 4; i++) {
            float mr = fmaxf(fmaxf(s[i][0], s[i][1]), fmaxf(s[i][2], s[i][3]));
            #pragma unroll
            for (int off = 8; off >= 1; off >>= 1)
                mr = fmaxf(mr, __shfl_xor_sync(0xffffffffu, mr, off));
            float mn = fmaxf(m_i[i], mr);
            float alpha = exp2f((m_i[i] - mn) * LOG2E);
            float p[4], rsum = 0.0f;
            #pragma unroll
            for (int j = 0; j < 4; j++) {
                p[j] = exp2f((s[i][j] - mn) * LOG2E);
                rsum += p[j];
            }
            #pragma unroll
            for (int off = 8; off >= 1; off >>= 1)
                rsum += __shfl_xor_sync(0xffffffffu, rsum, off);
            l_i[i] = l_i[i] * alpha + rsum;
            m_i[i] = mn;
            #pragma unroll
            for (int j = 0; j < 4; j++) acc[i][j] *= alpha;
            // stage P for the PV GEMM
            #pragma unroll
            for (int j = 0; j < 4; j++)
                Ps[(ty * 4 + i) * PS + tx * 4 + j] = p[j];
        }
        __syncthreads();

        // O += P @ V   (P broadcast-read per q-row, V via float4)
        #pragma unroll 8
        for (int kk = 0; kk < 64; kk++) {
            float p[4];
            #pragma unroll
            for (int i = 0; i < 4; i++)
                p[i] = Ps[(ty * 4 + i) * PS + kk];
            float v[4];
            *(float4*)v = *(const float4*)&Vs[kk * VS + tx * 4];
            #pragma unroll
            for (int i = 0; i < 4; i++)
                #pragma unroll
                for (int j = 0; j < 4; j++)
                    acc[i][j] = fmaf(p[i], v[j], acc[i][j]);
        }
    }

    // Normalize and write out [B, N, D] with D = h*64 + d
    float* go = out + ((size_t)b * Np + q0) * Dp + h * DHp;
    #pragma unroll
    for (int i = 0; i < 4; i++) {
        float inv = 1.0f / l_i[i];
        float4 o;
        o.x = acc[i][0] * inv;
        o.y = acc[i][1] * inv;
        o.z = acc[i][2] * inv;
        o.w = acc[i][3] * inv;
        *(float4*)&go[(size_t)(ty * 4 + i) * Dp + tx * 4] = o;
    }
}

// ---------------------------------------------------------------------------
extern "C" void kernel_launch(void* const* d_in, const int* in_sizes, int n_in,
                              void* d_out, int out_size)
{
    const float* x  = (const float*)d_in[0];
    const float* Wq = (const float*)d_in[1];
    const float* bq = (const float*)d_in[2];
    const float* Wk = (const float*)d_in[3];
    const float* bk = (const float*)d_in[4];
    const float* Wv = (const float*)d_in[5];
    const float* bv = (const float*)d_in[6];
    float* out = (float*)d_out;

    // QKV projections: grid (N-tiles=8, M-tiles=128, 3 matrices)
    dim3 g1(Dp / 64, Mp / 64, 3);
    qkv_kernel<<<g1, 256>>>(x, Wq, bq, Wk, bk, Wv, bv);

    // Flash attention: grid (Q-tiles=16, B*H=64)
    cudaFuncSetAttribute(attn_kernel,
                         cudaFuncAttributeMaxDynamicSharedMemorySize, ATTN_SMEM);
    dim3 g2(Np / 64, Bp * Hp);
    attn_kernel<<<g2, 256, ATTN_SMEM>>>(out);
}

// round 5
// speedup vs baseline: 1.0960x; 1.0960x over previous
#include <cuda_runtime.h>

// Problem constants
#define Bp   8
#define Np   1024
#define Dp   512
#define Hp   8
#define DHp  64
#define Mp   (Bp * Np)          // 8192 rows

// Scratch: Q/K/V in [B, H, N, DH] layout (16 MB each, static device globals)
__device__ float g_q[Bp * Hp * Np * DHp];
__device__ float g_k[Bp * Hp * Np * DHp];
__device__ float g_v[Bp * Hp * Np * DHp];

// ---------------------------------------------------------------------------
// Kernel 1: fused QKV projection GEMM.  C[m,c] = sum_k x[m,k]*W[k,c] + b[c]
// BM=128, BN=64, BK=16, 256 threads, 8x4 micro-tile (3 LDS.128 : 32 FFMA).
// blockIdx.z selects {Q,K,V}; output scattered into [B,H,N,DH] scratch.
// ---------------------------------------------------------------------------
__global__ __launch_bounds__(256) void qkv_kernel(
    const float* __restrict__ x,
    const float* __restrict__ Wq, const float* __restrict__ bq,
    const float* __restrict__ Wk, const float* __restrict__ bk,
    const float* __restrict__ Wv, const float* __restrict__ bv)
{
    __shared__ float Xs[16][132];   // [k][m], padded
    __shared__ float Ws[16][64];    // [k][n]

    const int which = blockIdx.z;
    const float* W    = (which == 0) ? Wq : (which == 1) ? Wk : Wv;
    const float* bias = (which == 0) ? bq : (which == 1) ? bk : bv;
    float* outp       = (which == 0) ? g_q : (which == 1) ? g_k : g_v;

    const int m0 = blockIdx.y * 128;
    const int nb = blockIdx.x * 64;
    const int tid = threadIdx.x;
    const int tx = tid & 15;       // n-fragment: 4 cols
    const int ty = tid >> 4;       // m-fragment: 8 rows

    float acc[8][4];
    #pragma unroll
    for (int i = 0; i < 8; i++)
        #pragma unroll
        for (int j = 0; j < 4; j++) acc[i][j] = 0.0f;

    const int xcol = tid & 15, xrow0 = tid >> 4;   // X loader: k-col, row group
    const int wcol = tid & 63, wrow0 = tid >> 6;   // W loader

    for (int kt = 0; kt < Dp; kt += 16) {
        // X tile [128 m][16 k] -> Xs[k][m] (transposed)
        #pragma unroll
        for (int p = 0; p < 8; p++) {
            int row = xrow0 + p * 16;
            Xs[xcol][row] = x[(size_t)(m0 + row) * Dp + kt + xcol];
        }
        // W tile [16 k][64 n]
        #pragma unroll
        for (int p = 0; p < 4; p++) {
            int r = wrow0 + p * 4;
            Ws[r][wcol] = W[(size_t)(kt + r) * Dp + nb + wcol];
        }
        __syncthreads();

        #pragma unroll
        for (int k = 0; k < 16; k++) {
            float a[8], w[4];
            *(float4*)&a[0] = *(const float4*)&Xs[k][ty * 8];
            *(float4*)&a[4] = *(const float4*)&Xs[k][ty * 8 + 4];
            *(float4*)&w[0] = *(const float4*)&Ws[k][tx * 4];
            #pragma unroll
            for (int i = 0; i < 8; i++)
                #pragma unroll
                for (int j = 0; j < 4; j++)
                    acc[i][j] = fmaf(a[i], w[j], acc[i][j]);
        }
        __syncthreads();
    }

    // Epilogue: bias + scatter to [B,H,N,DH]. nb 64-aligned -> one head per n-tile.
    float b4[4];
    #pragma unroll
    for (int j = 0; j < 4; j++) b4[j] = bias[nb + tx * 4 + j];
    const int h = nb >> 6;

    #pragma unroll
    for (int i = 0; i < 8; i++) {
        int gm = m0 + ty * 8 + i;
        int bb = gm >> 10;
        int nn = gm & 1023;
        float4 o;
        o.x = acc[i][0] + b4[0];
        o.y = acc[i][1] + b4[1];
        o.z = acc[i][2] + b4[2];
        o.w = acc[i][3] + b4[3];
        size_t addr = (((size_t)(bb * Hp + h)) * Np + nn) * DHp + tx * 4;
        *(float4*)&outp[addr] = o;
    }
}

// ---------------------------------------------------------------------------
// Kernel 2: flash attention per (b,h). BQ=128 Q rows per CTA, 64-key tiles.
// scores = Q K^T (NO 1/sqrt(dh) per reference), online softmax, O = P V.
// Thread map: tx = tid&15 -> 4 k/d cols; ty = tid>>4 -> 8 q rows.
// 16-lane tx groups are aligned warp halves -> shfl_xor reductions valid.
// ---------------------------------------------------------------------------
#define QS 132
#define KS 68
#define VS 68
#define PS 68
#define ATTN_SMEM ((64 * QS + 64 * KS + 64 * VS + 128 * PS) * 4)   // 103,424 B

__global__ __launch_bounds__(256) void attn_kernel(float* __restrict__ out)
{
    extern __shared__ float sm[];
    float* Qt = sm;                 // [64 d][QS]  (q-major transposed)
    float* Kt = Qt + 64 * QS;       // [64 d][KS]
    float* Vs = Kt + 64 * KS;       // [64 k][VS]
    float* Ps = Vs + 64 * VS;       // [128 q][PS]

    const int q0 = blockIdx.x * 128;
    const int bh = blockIdx.y;                 // b*H + h
    const int b  = bh >> 3, h = bh & 7;
    const int tid = threadIdx.x;
    const int tx = tid & 15, ty = tid >> 4;

    const float* gq = g_q + ((size_t)bh * Np + q0) * DHp;
    const float* gk = g_k + (size_t)bh * Np * DHp;
    const float* gv = g_v + (size_t)bh * Np * DHp;

    // Q tile [128 q][64 d] -> Qt[d][q]
    for (int idx = tid; idx < 128 * 64; idx += 256) {
        int q = idx >> 6, d = idx & 63;
        Qt[d * QS + q] = gq[idx];
    }

    float m_i[8], l_i[8], acc[8][4];
    #pragma unroll
    for (int i = 0; i < 8; i++) {
        m_i[i] = -1e30f; l_i[i] = 0.0f;
        #pragma unroll
        for (int j = 0; j < 4; j++) acc[i][j] = 0.0f;
    }

    const float LOG2E = 1.44269504088896340736f;

    for (int kt = 0; kt < Np; kt += 64) {
        __syncthreads();   // prior-iter Kt/Vs/Ps reads done (orders Q store on iter 0)

        // K tile transposed Kt[d][k], V tile row-major Vs[k][d]
        for (int idx = tid; idx < 64 * 64; idx += 256) {
            int k = idx >> 6, d = idx & 63;
            Kt[d * KS + k] = gk[kt * DHp + idx];
            Vs[k * VS + d] = gv[kt * DHp + idx];
        }
        __syncthreads();

        // ---- S = Q K^T : 8x4 per thread over d ----
        float s[8][4];
        #pragma unroll
        for (int i = 0; i < 8; i++)
            #pragma unroll
            for (int j = 0; j < 4; j++) s[i][j] = 0.0f;

        #pragma unroll 4
        for (int d = 0; d < 64; d++) {
            float a[8], kf[4];
            *(float4*)&a[0] = *(const float4*)&Qt[d * QS + ty * 8];
            *(float4*)&a[4] = *(const float4*)&Qt[d * QS + ty * 8 + 4];
            *(float4*)&kf[0] = *(const float4*)&Kt[d * KS + tx * 4];
            #pragma unroll
            for (int i = 0; i < 8; i++)
                #pragma unroll
                for (int j = 0; j < 4; j++)
                    s[i][j] = fmaf(a[i], kf[j], s[i][j]);
        }

        // ---- online softmax per q-row (reduce across 16 tx lanes) ----
        #pragma unroll
        for (int i = 0; i < 8; i++) {
            float mr = fmaxf(fmaxf(s[i][0], s[i][1]), fmaxf(s[i][2], s[i][3]));
            #pragma unroll
            for (int off = 8; off >= 1; off >>= 1)
                mr = fmaxf(mr, __shfl_xor_sync(0xffffffffu, mr, off));
            float mn = fmaxf(m_i[i], mr);
            float alpha = exp2f((m_i[i] - mn) * LOG2E);
            float4 p;
            p.x = exp2f((s[i][0] - mn) * LOG2E);
            p.y = exp2f((s[i][1] - mn) * LOG2E);
            p.z = exp2f((s[i][2] - mn) * LOG2E);
            p.w = exp2f((s[i][3] - mn) * LOG2E);
            float rsum = p.x + p.y + p.z + p.w;
            #pragma unroll
            for (int off = 8; off >= 1; off >>= 1)
                rsum += __shfl_xor_sync(0xffffffffu, rsum, off);
            l_i[i] = l_i[i] * alpha + rsum;
            m_i[i] = mn;
            #pragma unroll
            for (int j = 0; j < 4; j++) acc[i][j] *= alpha;
            *(float4*)&Ps[(ty * 8 + i) * PS + tx * 4] = p;   // stage P
        }
        __syncthreads();

        // ---- O += P @ V : P loaded as float4 per 4 k-steps ----
        #pragma unroll 2
        for (int kk0 = 0; kk0 < 64; kk0 += 4) {
            float4 pr[8];
            #pragma unroll
            for (int i = 0; i < 8; i++)
                pr[i] = *(const float4*)&Ps[(ty * 8 + i) * PS + kk0];
            #pragma unroll
            for (int kki = 0; kki < 4; kki++) {
                float v[4];
                *(float4*)&v[0] = *(const float4*)&Vs[(kk0 + kki) * VS + tx * 4];
                #pragma unroll
                for (int i = 0; i < 8; i++) {
                    float pv = (kki == 0) ? pr[i].x : (kki == 1) ? pr[i].y
                             : (kki == 2) ? pr[i].z : pr[i].w;
                    #pragma unroll
                    for (int j = 0; j < 4; j++)
                        acc[i][j] = fmaf(pv, v[j], acc[i][j]);
                }
            }
        }
    }

    // normalize + write out [B, N, D], D-col = h*64 + d
    float* go = out + ((size_t)b * Np + q0) * Dp + h * DHp;
    #pragma unroll
    for (int i = 0; i < 8; i++) {
        float inv = 1.0f / l_i[i];
        float4 o;
        o.x = acc[i][0] * inv;
        o.y = acc[i][1] * inv;
        o.z = acc[i][2] * inv;
        o.w = acc[i][3] * inv;
        *(float4*)&go[(size_t)(ty * 8 + i) * Dp + tx * 4] = o;
    }
}

// ---------------------------------------------------------------------------
extern "C" void kernel_launch(void* const* d_in, const int* in_sizes, int n_in,
                              void* d_out, int out_size)
{
    const float* x  = (const float*)d_in[0];
    const float* Wq = (const float*)d_in[1];
    const float* bq = (const float*)d_in[2];
    const float* Wk = (const float*)d_in[3];
    const float* bk = (const float*)d_in[4];
    const float* Wv = (const float*)d_in[5];
    const float* bv = (const float*)d_in[6];
    float* out = (float*)d_out;

    // QKV projections: grid (N-tiles=8, M-tiles=64, 3 matrices)
    dim3 g1(Dp / 64, Mp / 128, 3);
    qkv_kernel<<<g1, 256>>>(x, Wq, bq, Wk, bk, Wv, bv);

    // Flash attention: grid (Q-tiles=8, B*H=64)
    cudaFuncSetAttribute(attn_kernel,
                         cudaFuncAttributeMaxDynamicSharedMemorySize, ATTN_SMEM);
    dim3 g2(Np / 128, Bp * Hp);
    attn_kernel<<<g2, 256, ATTN_SMEM>>>(out);
}